// round 15
// baseline (speedup 1.0000x reference)
#include <cuda_runtime.h>
#include <cuda_fp16.h>
#include <math.h>
#include <cstdint>

// Problem constants
#define BB 2
#define SS 2048
#define DD 1024
#define HH 16
#define MM (BB * SS)          // 4096 rows

// Q pre-scale: 0.125 * log2(e)  (projection epilogue). p = 2^s directly.
#define QSCALE 0.1803368801f

// Scratch (allocation-free rule: __device__ globals)
__device__ __half g_I[(size_t)3 * MM * DD];   // fp16 inputs (q,k,v); reused for Ctx
__device__ __half g_W[(size_t)4 * DD * DD];   // weights fp16 (q,k,v,o)
__device__ __half g_Q[(size_t)MM * DD];       // Q fp16 (RoPE'd, pre-scaled)
__device__ __half g_K[(size_t)MM * DD];       // K fp16 (RoPE'd)
__device__ __half g_V[(size_t)MM * DD];       // V fp16

// ---------------------------------------------------------------------------
// Helpers
// ---------------------------------------------------------------------------
__device__ __forceinline__ uint32_t smem_u32(const void* p) {
    uint32_t a;
    asm("{ .reg .u64 t; cvta.to.shared.u64 t, %1; cvt.u32.u64 %0, t; }"
        : "=r"(a) : "l"(p));
    return a;
}

// fp16 x fp16 -> fp32 accum
__device__ __forceinline__ void mma16816h(float* c, const uint32_t* a, const uint32_t* b) {
    asm volatile(
        "mma.sync.aligned.m16n8k16.row.col.f32.f16.f16.f32 "
        "{%0,%1,%2,%3}, {%4,%5,%6,%7}, {%8,%9}, {%0,%1,%2,%3};"
        : "+f"(c[0]), "+f"(c[1]), "+f"(c[2]), "+f"(c[3])
        : "r"(a[0]), "r"(a[1]), "r"(a[2]), "r"(a[3]), "r"(b[0]), "r"(b[1]));
}

// fp16 x fp16 -> fp16 accum (D packed fp16x2; used for QK^T scores)
__device__ __forceinline__ void mma16816hh(uint32_t* c, const uint32_t* a, const uint32_t* b) {
    asm volatile(
        "mma.sync.aligned.m16n8k16.row.col.f16.f16.f16.f16 "
        "{%0,%1}, {%2,%3,%4,%5}, {%6,%7}, {%0,%1};"
        : "+r"(c[0]), "+r"(c[1])
        : "r"(a[0]), "r"(a[1]), "r"(a[2]), "r"(a[3]), "r"(b[0]), "r"(b[1]));
}

__device__ __forceinline__ void ldsm4(uint32_t* r, uint32_t addr) {
    asm volatile("ldmatrix.sync.aligned.m8n8.x4.shared.b16 {%0,%1,%2,%3}, [%4];"
        : "=r"(r[0]), "=r"(r[1]), "=r"(r[2]), "=r"(r[3]) : "r"(addr));
}

__device__ __forceinline__ void ldsm4t(uint32_t* r, uint32_t addr) {
    asm volatile("ldmatrix.sync.aligned.m8n8.x4.trans.shared.b16 {%0,%1,%2,%3}, [%4];"
        : "=r"(r[0]), "=r"(r[1]), "=r"(r[2]), "=r"(r[3]) : "r"(addr));
}

__device__ __forceinline__ void cpa16(uint32_t saddr, const void* g) {
    asm volatile("cp.async.cg.shared.global [%0], [%1], 16;" :: "r"(saddr), "l"(g));
}
#define CP_COMMIT() asm volatile("cp.async.commit_group;" ::: "memory")
#define CP_WAIT(n)  asm volatile("cp.async.wait_group %0;" :: "n"(n) : "memory")

// 2^x elementwise on a packed fp16x2 register (one MUFU op)
__device__ __forceinline__ uint32_t ex2r(uint32_t x) {
    uint32_t r;
    asm("ex2.approx.f16x2 %0, %1;" : "=r"(r) : "r"(x));
    return r;
}

__device__ __forceinline__ void store2_h(__half* H, size_t off, float v0, float v1) {
    __half2 hh; hh.x = __float2half_rn(v0); hh.y = __float2half_rn(v1);
    *(__half2*)(H + off) = hh;
}

// ---------------------------------------------------------------------------
// Batched fp32 -> fp16 convert, 4 independent float4 per thread (MLP=4).
// Each block covers 1024 consecutive float4 chunks, fully inside one region
// (regions are multiples of 2^18 float4s, 1024-aligned).
// ---------------------------------------------------------------------------
__global__ void cvt_all_kernel(
    const float4* __restrict__ q, const float4* __restrict__ k,
    const float4* __restrict__ v,
    const float4* __restrict__ wq, const float4* __restrict__ wk,
    const float4* __restrict__ wv, const float4* __restrict__ wo,
    ushort4* __restrict__ I, ushort4* __restrict__ W)
{
    int i0 = blockIdx.x * 1024 + threadIdx.x;
    const float4* s;
    ushort4* d;
    if (i0 < (3 << 20)) {
        int z = i0 >> 20;
        s = ((z == 0) ? q : ((z == 1) ? k : v)) + (i0 & ((1 << 20) - 1));
        d = I + i0;
    } else {
        int j0 = i0 - (3 << 20);
        int z = j0 >> 18;
        s = ((z == 0) ? wq : ((z == 1) ? wk : ((z == 2) ? wv : wo))) + (j0 & ((1 << 18) - 1));
        d = W + j0;
    }
    float4 v4[4];
#pragma unroll
    for (int j = 0; j < 4; j++) v4[j] = s[j * 256];
#pragma unroll
    for (int j = 0; j < 4; j++) {
        ushort4 h;
        h.x = __half_as_ushort(__float2half_rn(v4[j].x));
        h.y = __half_as_ushort(__float2half_rn(v4[j].y));
        h.z = __half_as_ushort(__float2half_rn(v4[j].z));
        h.w = __half_as_ushort(__float2half_rn(v4[j].w));
        d[j * 256] = h;
    }
}

// ---------------------------------------------------------------------------
// GEMM (unchanged from round 14 — passing): C = A @ W^T + bias, fp16 operands,
// fp32 accum. Block 128x128, BK=64, 256 threads, 3-stage cp.async.
// ---------------------------------------------------------------------------
template <int MODE>
__global__ __launch_bounds__(256, 2) void mma_gemm(
    const __half* __restrict__ Abase, const __half* __restrict__ Wbase,
    const float* __restrict__ bias0, const float* __restrict__ bias1,
    const float* __restrict__ bias2,
    float* __restrict__ Cout,
    __half* __restrict__ Qp, __half* __restrict__ Kp, __half* __restrict__ Vp)
{
    extern __shared__ __align__(1024) char sm[];
    const uint32_t smb = smem_u32(sm);
    const int tid = threadIdx.x;
    const int lane = tid & 31;
    const int warp = tid >> 5;
    const int wm = warp >> 1;
    const int wn = warp & 1;
    const int m0 = blockIdx.y * 128;
    const int n0 = blockIdx.x * 128;
    const int z = (MODE == 1) ? blockIdx.z : 0;

    const __half* A = Abase + (MODE == 1 ? (size_t)z * MM * DD : 0);
    const __half* W = Wbase + (MODE == 1 ? (size_t)z * DD * DD : 0);
    const float* bias = (MODE == 0) ? bias0
                        : ((z == 0) ? bias0 : ((z == 1) ? bias1 : bias2));

    float acc[2][8][4];
#pragma unroll
    for (int i = 0; i < 2; i++)
#pragma unroll
        for (int j = 0; j < 8; j++)
#pragma unroll
            for (int k = 0; k < 4; k++) acc[i][j][k] = 0.f;

    const __half* gp[2] = { A + (size_t)m0 * DD, W + (size_t)n0 * DD };
    int ltile[8], lrow[8], lcol[8];
#pragma unroll
    for (int i = 0; i < 8; i++) {
        int unit = tid + i * 256;
        ltile[i] = unit >> 10;
        int rem = unit & 1023;
        lrow[i] = rem >> 3;
        lcol[i] = rem & 7;
    }

    int aRow[2];
#pragma unroll
    for (int mf = 0; mf < 2; mf++)
        aRow[mf] = wm * 32 + mf * 16 + (lane & 7) + ((lane >> 3) & 1) * 8;
    const int cA = lane >> 4;
    int bRow[4];
#pragma unroll
    for (int nj = 0; nj < 4; nj++)
        bRow[nj] = wn * 64 + nj * 16 + (lane & 7) + (lane >> 4) * 8;
    const int cB = (lane >> 3) & 1;

#define G_ISSUE(st, k0)                                                        \
    do {                                                                       \
        uint32_t stb_ = smb + (st) * 32768;                                    \
        _Pragma("unroll")                                                      \
        for (int i = 0; i < 8; i++) {                                          \
            uint32_t dst = stb_ + ltile[i] * 16384 + lrow[i] * 128 +           \
                           (((lcol[i] ^ (lrow[i] & 7)) << 4));                 \
            cpa16(dst, gp[ltile[i]] + (size_t)lrow[i] * DD + (k0) + lcol[i] * 8); \
        }                                                                      \
    } while (0)

    G_ISSUE(0, 0);
    CP_COMMIT();
    G_ISSUE(1, 64);
    CP_COMMIT();

    int stage = 0, stage2 = 2;
    for (int it = 0; it < 16; it++) {
        if (it < 15) { CP_WAIT(1); } else { CP_WAIT(0); }
        __syncthreads();
        if (it < 14) {
            G_ISSUE(stage2, (it + 2) * 64);
            CP_COMMIT();
        }
        const uint32_t stb = smb + stage * 32768;
#pragma unroll
        for (int kk = 0; kk < 4; kk++) {
            uint32_t ah[2][4];
#pragma unroll
            for (int mf = 0; mf < 2; mf++) {
                uint32_t off = stb + aRow[mf] * 128 + (((2 * kk + cA) ^ (aRow[mf] & 7)) << 4);
                ldsm4(ah[mf], off);
            }
#pragma unroll
            for (int nj = 0; nj < 4; nj++) {
                uint32_t off = stb + 16384 + bRow[nj] * 128 + (((2 * kk + cB) ^ (bRow[nj] & 7)) << 4);
                uint32_t r4[4];
                ldsm4(r4, off);
#pragma unroll
                for (int mf = 0; mf < 2; mf++) {
                    mma16816h(acc[mf][2 * nj],     ah[mf], r4);
                    mma16816h(acc[mf][2 * nj + 1], ah[mf], r4 + 2);
                }
            }
        }
        stage = (stage == 2) ? 0 : stage + 1;
        stage2 = (stage2 == 2) ? 0 : stage2 + 1;
    }

    // -------------------- Epilogue --------------------
    if (MODE == 0) {
#pragma unroll
        for (int mf = 0; mf < 2; mf++) {
            int rbase = m0 + wm * 32 + mf * 16 + (lane >> 2);
#pragma unroll
            for (int nf = 0; nf < 8; nf++) {
                int col = n0 + wn * 64 + nf * 8 + (lane & 3) * 2;
                float b0 = bias[col], b1 = bias[col + 1];
#pragma unroll
                for (int half_ = 0; half_ < 2; half_++) {
                    int r = rbase + half_ * 8;
                    *(float2*)&Cout[(size_t)r * DD + col] =
                        make_float2(acc[mf][nf][2 * half_] + b0,
                                    acc[mf][nf][2 * half_ + 1] + b1);
                }
            }
        }
    } else {
        __half* OUT = (z == 0) ? Qp : ((z == 1) ? Kp : Vp);
        if (z < 2) {
            const float osc = (z == 0) ? QSCALE : 1.0f;
#pragma unroll
            for (int nf = 0; nf < 4; nf++) {
                int d0 = nf * 8 + (lane & 3) * 2;
                int col = n0 + wn * 64 + d0;
                int h = col >> 6;
                float bi00 = bias[col],      bi01 = bias[col + 1];
                float bi10 = bias[col + 32], bi11 = bias[col + 33];
                float if0 = powf(10000.0f, -(float)d0 * (1.0f / 32.0f));
                float if1 = powf(10000.0f, -(float)(d0 + 1) * (1.0f / 32.0f));
#pragma unroll
                for (int mf = 0; mf < 2; mf++) {
                    int rbase = m0 + wm * 32 + mf * 16 + (lane >> 2);
#pragma unroll
                    for (int half_ = 0; half_ < 2; half_++) {
                        int r = rbase + half_ * 8;
                        int b = r >> 11, s = r & (SS - 1);
                        size_t base = (((size_t)(b * HH + h)) << 17) + ((size_t)s << 6);
                        float x00 = acc[mf][nf][2 * half_]     + bi00;
                        float x01 = acc[mf][nf][2 * half_ + 1] + bi01;
                        float x10 = acc[mf][nf + 4][2 * half_]     + bi10;
                        float x11 = acc[mf][nf + 4][2 * half_ + 1] + bi11;
                        float sn0, cs0, sn1, cs1;
                        sincosf((float)s * if0, &sn0, &cs0);
                        sincosf((float)s * if1, &sn1, &cs1);
                        store2_h(OUT, base + d0,
                                 (x00 * cs0 - x10 * sn0) * osc,
                                 (x01 * cs1 - x11 * sn1) * osc);
                        store2_h(OUT, base + d0 + 32,
                                 (x10 * cs0 + x00 * sn0) * osc,
                                 (x11 * cs1 + x01 * sn1) * osc);
                    }
                }
            }
        } else {
#pragma unroll
            for (int nf = 0; nf < 8; nf++) {
                int col = n0 + wn * 64 + nf * 8 + (lane & 3) * 2;
                int h = col >> 6, d = col & 63;
                float b0 = bias[col], b1 = bias[col + 1];
#pragma unroll
                for (int mf = 0; mf < 2; mf++) {
                    int rbase = m0 + wm * 32 + mf * 16 + (lane >> 2);
#pragma unroll
                    for (int half_ = 0; half_ < 2; half_++) {
                        int r = rbase + half_ * 8;
                        int b = r >> 11, s = r & (SS - 1);
                        size_t base = (((size_t)(b * HH + h)) << 17) + ((size_t)s << 6);
                        store2_h(OUT, base + d,
                                 acc[mf][nf][2 * half_] + b0,
                                 acc[mf][nf][2 * half_ + 1] + b1);
                    }
                }
            }
        }
    }
#undef G_ISSUE
}

// ---------------------------------------------------------------------------
// Flash attention v2: 128 threads (4 warps), each warp owns 32 q-rows
// (2 mf-groups of 16) — K/V fragments are shared across 2x the outputs,
// HALVING per-SM ldmatrix traffic (the measured bottleneck).
// Same math as round 14: fp16-acc QK^T in log2 domain, ex2 in place,
// fp32-acc PV + ones-mma L. 128-key blocks, 3-stage cp.async, one sync/iter.
// smem (112KB): Q 0..16K; stages at 16384 + st*32768 (K 16KB, V 16KB).
// ---------------------------------------------------------------------------
__global__ __launch_bounds__(128, 2) void mma_attn(
    const __half* __restrict__ Q, const __half* __restrict__ K,
    const __half* __restrict__ V, __half* __restrict__ Ctx)
{
    extern __shared__ __align__(1024) char sm[];
    const uint32_t smb = smem_u32(sm);
    const int tid = threadIdx.x;
    const int lane = tid & 31;
    const int warp = tid >> 5;          // 0..3, each owns 32 q-rows
    const int bh = blockIdx.y;
    const int q0 = blockIdx.x * 128;

    const size_t hb = ((size_t)bh << 17);
    const __half* Qp = Q + hb + (size_t)q0 * 64;
    const __half* tp[2] = { K + hb, V + hb };

    // ---- stage Q (128x64 fp16 = 1024 chunks): 8 chunks/thread
#pragma unroll
    for (int i = 0; i < 8; i++) {
        int unit = tid + i * 128;
        int row = unit >> 3, c = unit & 7;
        uint32_t dst = smb + row * 128 + (((c ^ (row & 7)) << 4));
        cpa16(dst, Qp + (size_t)row * 64 + c * 8);
    }
    CP_COMMIT();

    // K/V stage-load geometry: 16 chunks/thread (32KB per stage)
    int ktile[16], krow[16], kcol[16];
#pragma unroll
    for (int i = 0; i < 16; i++) {
        int unit = tid + i * 128;
        ktile[i] = unit >> 10;          // 0 = K, 1 = V
        int rem = unit & 1023;
        krow[i] = rem >> 3;
        kcol[i] = rem & 7;
    }

#define A_ISSUE(st, blk)                                                       \
    do {                                                                       \
        uint32_t stb_ = smb + 16384 + (st) * 32768;                            \
        _Pragma("unroll")                                                      \
        for (int i = 0; i < 16; i++) {                                         \
            uint32_t dst = stb_ + ktile[i] * 16384 + krow[i] * 128 +           \
                           (((kcol[i] ^ (krow[i] & 7)) << 4));                 \
            cpa16(dst, tp[ktile[i]] + ((size_t)((blk) * 128 + krow[i])) * 64 + kcol[i] * 8); \
        }                                                                      \
    } while (0)

    A_ISSUE(0, 0);
    CP_COMMIT();
    A_ISSUE(1, 1);
    CP_COMMIT();

    // ---- Q fragments persistent: 2 mf-groups x 4 kk
    CP_WAIT(2);
    __syncthreads();
    const int cQ = lane >> 4;
    int rowQ[2];
    uint32_t qf[2][4][4];
#pragma unroll
    for (int mf = 0; mf < 2; mf++) {
        rowQ[mf] = warp * 32 + mf * 16 + (lane & 7) + ((lane >> 3) & 1) * 8;
#pragma unroll
        for (int kk = 0; kk < 4; kk++) {
            uint32_t off = smb + rowQ[mf] * 128 + (((2 * kk + cQ) ^ (rowQ[mf] & 7)) << 4);
            ldsm4(qf[mf][kk], off);
        }
    }

    float o[2][8][4];
#pragma unroll
    for (int mf = 0; mf < 2; mf++)
#pragma unroll
        for (int i = 0; i < 8; i++)
#pragma unroll
            for (int j = 0; j < 4; j++) o[mf][i][j] = 0.f;
    float accL[2][4];
#pragma unroll
    for (int mf = 0; mf < 2; mf++)
#pragma unroll
        for (int j = 0; j < 4; j++) accL[mf][j] = 0.f;
    const uint32_t ones2[2] = {0x3C003C00u, 0x3C003C00u};

    const int rK = (lane & 7) + (lane >> 4) * 8;
    const int cK = (lane >> 3) & 1;
    const int rV = (lane & 7) + ((lane >> 3) & 1) * 8;
    const int cV = lane >> 4;

    int stage = 0, stage2 = 2;
    for (int it = 0; it < 16; it++) {
        if (it < 15) { CP_WAIT(1); } else { CP_WAIT(0); }
        __syncthreads();
        if (it < 14) {
            A_ISSUE(stage2, it + 2);
            CP_COMMIT();
        }
        const uint32_t stb = smb + 16384 + stage * 32768;

#pragma unroll
        for (int h = 0; h < 2; h++) {       // two 64-key halves per block
            const uint32_t kb_ = stb + h * 8192;
            const uint32_t vb_ = stb + 16384 + h * 8192;

            // ---- S = Q K^T, fp16 accumulation; each K frag feeds BOTH mf
            uint32_t sh[2][8][2];
#pragma unroll
            for (int mf = 0; mf < 2; mf++)
#pragma unroll
                for (int i = 0; i < 8; i++) { sh[mf][i][0] = 0u; sh[mf][i][1] = 0u; }

#pragma unroll
            for (int kk = 0; kk < 4; kk++) {
#pragma unroll
                for (int nj = 0; nj < 4; nj++) {
                    int row = nj * 16 + rK;
                    uint32_t off = kb_ + row * 128 + (((2 * kk + cK) ^ (row & 7)) << 4);
                    uint32_t r4[4];
                    ldsm4(r4, off);
#pragma unroll
                    for (int mf = 0; mf < 2; mf++) {
                        mma16816hh(sh[mf][2 * nj],     qf[mf][kk], r4);
                        mma16816hh(sh[mf][2 * nj + 1], qf[mf][kk], r4 + 2);
                    }
                }
            }

            // ---- p = 2^s in-place on packed fp16x2 accumulators
            uint32_t ph[2][4][4];
#pragma unroll
            for (int mf = 0; mf < 2; mf++)
#pragma unroll
                for (int j = 0; j < 4; j++) {
                    ph[mf][j][0] = ex2r(sh[mf][2 * j][0]);
                    ph[mf][j][1] = ex2r(sh[mf][2 * j][1]);
                    ph[mf][j][2] = ex2r(sh[mf][2 * j + 1][0]);
                    ph[mf][j][3] = ex2r(sh[mf][2 * j + 1][1]);
                }

            // ---- O += P V; L += P·1; each V frag feeds BOTH mf
#pragma unroll
            for (int j = 0; j < 4; j++) {
                int row = j * 16 + rV;
#pragma unroll
                for (int u = 0; u < 4; u++) {
                    uint32_t off = vb_ + row * 128 + (((2 * u + cV) ^ (row & 7)) << 4);
                    uint32_t r4[4];
                    ldsm4t(r4, off);
#pragma unroll
                    for (int mf = 0; mf < 2; mf++) {
                        mma16816h(o[mf][2 * u],     ph[mf][j], r4);
                        mma16816h(o[mf][2 * u + 1], ph[mf][j], r4 + 2);
                    }
                }
#pragma unroll
                for (int mf = 0; mf < 2; mf++)
                    mma16816h(accL[mf], ph[mf][j], ones2);
            }
        }
        stage = (stage == 2) ? 0 : stage + 1;
        stage2 = (stage2 == 2) ? 0 : stage2 + 1;
    }

    // ---- writeout: Ctx fp16, [B*S, 1024]
    int b = bh >> 4, h = bh & 15;
#pragma unroll
    for (int mf = 0; mf < 2; mf++) {
        float inv0 = 1.f / accL[mf][0], inv1 = 1.f / accL[mf][2];
        int srow = q0 + warp * 32 + mf * 16 + (lane >> 2);
#pragma unroll
        for (int nf = 0; nf < 8; nf++) {
            int d = nf * 8 + (lane & 3) * 2;
            size_t off0 = ((size_t)(b * SS + srow)) * DD + h * 64 + d;
            store2_h(Ctx, off0, o[mf][nf][0] * inv0, o[mf][nf][1] * inv0);
            size_t off1 = ((size_t)(b * SS + srow + 8)) * DD + h * 64 + d;
            store2_h(Ctx, off1, o[mf][nf][2] * inv1, o[mf][nf][3] * inv1);
        }
    }
#undef A_ISSUE
}

// ---------------------------------------------------------------------------
extern "C" void kernel_launch(void* const* d_in, const int* in_sizes, int n_in,
                              void* d_out, int out_size)
{
    const float* query = (const float*)d_in[0];
    const float* key   = (const float*)d_in[1];
    const float* value = (const float*)d_in[2];
    const float* Wq    = (const float*)d_in[3];
    const float* bq    = (const float*)d_in[4];
    const float* Wk    = (const float*)d_in[5];
    const float* bk    = (const float*)d_in[6];
    const float* Wv    = (const float*)d_in[7];
    const float* bv    = (const float*)d_in[8];
    const float* Wo    = (const float*)d_in[9];
    const float* bo    = (const float*)d_in[10];

    __half *Ip, *Wp, *Qp, *Kp, *Vp;
    cudaGetSymbolAddress((void**)&Ip, g_I);
    cudaGetSymbolAddress((void**)&Wp, g_W);
    cudaGetSymbolAddress((void**)&Qp, g_Q);
    cudaGetSymbolAddress((void**)&Kp, g_K);
    cudaGetSymbolAddress((void**)&Vp, g_V);

    cudaFuncSetAttribute(mma_gemm<0>, cudaFuncAttributeMaxDynamicSharedMemorySize, 98304);
    cudaFuncSetAttribute(mma_gemm<1>, cudaFuncAttributeMaxDynamicSharedMemorySize, 98304);
    cudaFuncSetAttribute(mma_attn, cudaFuncAttributeMaxDynamicSharedMemorySize, 114688);

    // 1) convert inputs + weights to fp16 (one launch, MLP=4)
    const int total4 = (3 << 20) + (4 << 18);   // 4,194,304 float4s
    cvt_all_kernel<<<total4 / 1024, 256>>>(
        (const float4*)query, (const float4*)key, (const float4*)value,
        (const float4*)Wq, (const float4*)Wk, (const float4*)Wv, (const float4*)Wo,
        (ushort4*)Ip, (ushort4*)Wp);

    // 2) fused QKV projection + bias + RoPE (+QSCALE on Q) -> fp16 Q/K/V
    dim3 pg(DD / 128, MM / 128, 3);
    mma_gemm<1><<<pg, 256, 98304>>>(Ip, Wp, bq, bk, bv,
                                    nullptr, Qp, Kp, Vp);

    // 3) attention -> Ctx fp16 (reuse input buffer); 128 threads/CTA
    dim3 ag(SS / 128, BB * HH);
    mma_attn<<<ag, 128, 114688>>>(Qp, Kp, Vp, Ip);

    // 4) O projection -> d_out (fp32)
    dim3 og(DD / 128, MM / 128, 1);
    mma_gemm<0><<<og, 256, 98304>>>(Ip, Wp + (size_t)3 * DD * DD,
                                    bo, nullptr, nullptr,
                                    (float*)d_out, nullptr, nullptr, nullptr);
}

// round 16
// speedup vs baseline: 1.0317x; 1.0317x over previous
#include <cuda_runtime.h>
#include <cuda_fp16.h>
#include <math.h>
#include <cstdint>

// Problem constants
#define BB 2
#define SS 2048
#define DD 1024
#define HH 16
#define MM (BB * SS)          // 4096 rows

// Q pre-scale: 0.125 * log2(e)  (projection epilogue). p = 2^s directly.
#define QSCALE 0.1803368801f

// Scratch (allocation-free rule: __device__ globals)
__device__ __half g_I[(size_t)3 * MM * DD];   // fp16 inputs (q,k,v); reused for Ctx
__device__ __half g_W[(size_t)4 * DD * DD];   // weights fp16 (q,k,v,o)
__device__ __half g_Q[(size_t)MM * DD];       // Q fp16 (RoPE'd, pre-scaled)
__device__ __half g_K[(size_t)MM * DD];       // K fp16 (RoPE'd)
__device__ __half g_V[(size_t)MM * DD];       // V fp16

// ---------------------------------------------------------------------------
// Helpers
// ---------------------------------------------------------------------------
__device__ __forceinline__ uint32_t smem_u32(const void* p) {
    uint32_t a;
    asm("{ .reg .u64 t; cvta.to.shared.u64 t, %1; cvt.u32.u64 %0, t; }"
        : "=r"(a) : "l"(p));
    return a;
}

// fp16 x fp16 -> fp32 accum
__device__ __forceinline__ void mma16816h(float* c, const uint32_t* a, const uint32_t* b) {
    asm volatile(
        "mma.sync.aligned.m16n8k16.row.col.f32.f16.f16.f32 "
        "{%0,%1,%2,%3}, {%4,%5,%6,%7}, {%8,%9}, {%0,%1,%2,%3};"
        : "+f"(c[0]), "+f"(c[1]), "+f"(c[2]), "+f"(c[3])
        : "r"(a[0]), "r"(a[1]), "r"(a[2]), "r"(a[3]), "r"(b[0]), "r"(b[1]));
}

// fp16 x fp16 -> fp16 accum (D packed fp16x2; used for QK^T scores)
__device__ __forceinline__ void mma16816hh(uint32_t* c, const uint32_t* a, const uint32_t* b) {
    asm volatile(
        "mma.sync.aligned.m16n8k16.row.col.f16.f16.f16.f16 "
        "{%0,%1}, {%2,%3,%4,%5}, {%6,%7}, {%0,%1};"
        : "+r"(c[0]), "+r"(c[1])
        : "r"(a[0]), "r"(a[1]), "r"(a[2]), "r"(a[3]), "r"(b[0]), "r"(b[1]));
}

__device__ __forceinline__ void ldsm4(uint32_t* r, uint32_t addr) {
    asm volatile("ldmatrix.sync.aligned.m8n8.x4.shared.b16 {%0,%1,%2,%3}, [%4];"
        : "=r"(r[0]), "=r"(r[1]), "=r"(r[2]), "=r"(r[3]) : "r"(addr));
}

__device__ __forceinline__ void ldsm4t(uint32_t* r, uint32_t addr) {
    asm volatile("ldmatrix.sync.aligned.m8n8.x4.trans.shared.b16 {%0,%1,%2,%3}, [%4];"
        : "=r"(r[0]), "=r"(r[1]), "=r"(r[2]), "=r"(r[3]) : "r"(addr));
}

__device__ __forceinline__ void cpa16(uint32_t saddr, const void* g) {
    asm volatile("cp.async.cg.shared.global [%0], [%1], 16;" :: "r"(saddr), "l"(g));
}
#define CP_COMMIT() asm volatile("cp.async.commit_group;" ::: "memory")
#define CP_WAIT(n)  asm volatile("cp.async.wait_group %0;" :: "n"(n) : "memory")

// 2^x elementwise on a packed fp16x2 register (one MUFU op)
__device__ __forceinline__ uint32_t ex2r(uint32_t x) {
    uint32_t r;
    asm("ex2.approx.f16x2 %0, %1;" : "=r"(r) : "r"(x));
    return r;
}

__device__ __forceinline__ void store2_h(__half* H, size_t off, float v0, float v1) {
    __half2 hh; hh.x = __float2half_rn(v0); hh.y = __float2half_rn(v1);
    *(__half2*)(H + off) = hh;
}

// ---------------------------------------------------------------------------
// Batched fp32 -> fp16 convert, 4 independent float4 per thread (MLP=4).
// ---------------------------------------------------------------------------
__global__ void cvt_all_kernel(
    const float4* __restrict__ q, const float4* __restrict__ k,
    const float4* __restrict__ v,
    const float4* __restrict__ wq, const float4* __restrict__ wk,
    const float4* __restrict__ wv, const float4* __restrict__ wo,
    ushort4* __restrict__ I, ushort4* __restrict__ W)
{
    int i0 = blockIdx.x * 1024 + threadIdx.x;
    const float4* s;
    ushort4* d;
    if (i0 < (3 << 20)) {
        int z = i0 >> 20;
        s = ((z == 0) ? q : ((z == 1) ? k : v)) + (i0 & ((1 << 20) - 1));
        d = I + i0;
    } else {
        int j0 = i0 - (3 << 20);
        int z = j0 >> 18;
        s = ((z == 0) ? wq : ((z == 1) ? wk : ((z == 2) ? wv : wo))) + (j0 & ((1 << 18) - 1));
        d = W + j0;
    }
    float4 v4[4];
#pragma unroll
    for (int j = 0; j < 4; j++) v4[j] = s[j * 256];
#pragma unroll
    for (int j = 0; j < 4; j++) {
        ushort4 h;
        h.x = __half_as_ushort(__float2half_rn(v4[j].x));
        h.y = __half_as_ushort(__float2half_rn(v4[j].y));
        h.z = __half_as_ushort(__float2half_rn(v4[j].z));
        h.w = __half_as_ushort(__float2half_rn(v4[j].w));
        d[j * 256] = h;
    }
}

// ---------------------------------------------------------------------------
// GEMM (unchanged — passing): C = A @ W^T + bias, fp16 operands, fp32 accum.
// Block 128x128, BK=64, 256 threads, 3-stage cp.async.
// ---------------------------------------------------------------------------
template <int MODE>
__global__ __launch_bounds__(256, 2) void mma_gemm(
    const __half* __restrict__ Abase, const __half* __restrict__ Wbase,
    const float* __restrict__ bias0, const float* __restrict__ bias1,
    const float* __restrict__ bias2,
    float* __restrict__ Cout,
    __half* __restrict__ Qp, __half* __restrict__ Kp, __half* __restrict__ Vp)
{
    extern __shared__ __align__(1024) char sm[];
    const uint32_t smb = smem_u32(sm);
    const int tid = threadIdx.x;
    const int lane = tid & 31;
    const int warp = tid >> 5;
    const int wm = warp >> 1;
    const int wn = warp & 1;
    const int m0 = blockIdx.y * 128;
    const int n0 = blockIdx.x * 128;
    const int z = (MODE == 1) ? blockIdx.z : 0;

    const __half* A = Abase + (MODE == 1 ? (size_t)z * MM * DD : 0);
    const __half* W = Wbase + (MODE == 1 ? (size_t)z * DD * DD : 0);
    const float* bias = (MODE == 0) ? bias0
                        : ((z == 0) ? bias0 : ((z == 1) ? bias1 : bias2));

    float acc[2][8][4];
#pragma unroll
    for (int i = 0; i < 2; i++)
#pragma unroll
        for (int j = 0; j < 8; j++)
#pragma unroll
            for (int k = 0; k < 4; k++) acc[i][j][k] = 0.f;

    const __half* gp[2] = { A + (size_t)m0 * DD, W + (size_t)n0 * DD };
    int ltile[8], lrow[8], lcol[8];
#pragma unroll
    for (int i = 0; i < 8; i++) {
        int unit = tid + i * 256;
        ltile[i] = unit >> 10;
        int rem = unit & 1023;
        lrow[i] = rem >> 3;
        lcol[i] = rem & 7;
    }

    int aRow[2];
#pragma unroll
    for (int mf = 0; mf < 2; mf++)
        aRow[mf] = wm * 32 + mf * 16 + (lane & 7) + ((lane >> 3) & 1) * 8;
    const int cA = lane >> 4;
    int bRow[4];
#pragma unroll
    for (int nj = 0; nj < 4; nj++)
        bRow[nj] = wn * 64 + nj * 16 + (lane & 7) + (lane >> 4) * 8;
    const int cB = (lane >> 3) & 1;

#define G_ISSUE(st, k0)                                                        \
    do {                                                                       \
        uint32_t stb_ = smb + (st) * 32768;                                    \
        _Pragma("unroll")                                                      \
        for (int i = 0; i < 8; i++) {                                          \
            uint32_t dst = stb_ + ltile[i] * 16384 + lrow[i] * 128 +           \
                           (((lcol[i] ^ (lrow[i] & 7)) << 4));                 \
            cpa16(dst, gp[ltile[i]] + (size_t)lrow[i] * DD + (k0) + lcol[i] * 8); \
        }                                                                      \
    } while (0)

    G_ISSUE(0, 0);
    CP_COMMIT();
    G_ISSUE(1, 64);
    CP_COMMIT();

    int stage = 0, stage2 = 2;
    for (int it = 0; it < 16; it++) {
        if (it < 15) { CP_WAIT(1); } else { CP_WAIT(0); }
        __syncthreads();
        if (it < 14) {
            G_ISSUE(stage2, (it + 2) * 64);
            CP_COMMIT();
        }
        const uint32_t stb = smb + stage * 32768;
#pragma unroll
        for (int kk = 0; kk < 4; kk++) {
            uint32_t ah[2][4];
#pragma unroll
            for (int mf = 0; mf < 2; mf++) {
                uint32_t off = stb + aRow[mf] * 128 + (((2 * kk + cA) ^ (aRow[mf] & 7)) << 4);
                ldsm4(ah[mf], off);
            }
#pragma unroll
            for (int nj = 0; nj < 4; nj++) {
                uint32_t off = stb + 16384 + bRow[nj] * 128 + (((2 * kk + cB) ^ (bRow[nj] & 7)) << 4);
                uint32_t r4[4];
                ldsm4(r4, off);
#pragma unroll
                for (int mf = 0; mf < 2; mf++) {
                    mma16816h(acc[mf][2 * nj],     ah[mf], r4);
                    mma16816h(acc[mf][2 * nj + 1], ah[mf], r4 + 2);
                }
            }
        }
        stage = (stage == 2) ? 0 : stage + 1;
        stage2 = (stage2 == 2) ? 0 : stage2 + 1;
    }

    // -------------------- Epilogue --------------------
    if (MODE == 0) {
#pragma unroll
        for (int mf = 0; mf < 2; mf++) {
            int rbase = m0 + wm * 32 + mf * 16 + (lane >> 2);
#pragma unroll
            for (int nf = 0; nf < 8; nf++) {
                int col = n0 + wn * 64 + nf * 8 + (lane & 3) * 2;
                float b0 = bias[col], b1 = bias[col + 1];
#pragma unroll
                for (int half_ = 0; half_ < 2; half_++) {
                    int r = rbase + half_ * 8;
                    *(float2*)&Cout[(size_t)r * DD + col] =
                        make_float2(acc[mf][nf][2 * half_] + b0,
                                    acc[mf][nf][2 * half_ + 1] + b1);
                }
            }
        }
    } else {
        __half* OUT = (z == 0) ? Qp : ((z == 1) ? Kp : Vp);
        if (z < 2) {
            const float osc = (z == 0) ? QSCALE : 1.0f;
#pragma unroll
            for (int nf = 0; nf < 4; nf++) {
                int d0 = nf * 8 + (lane & 3) * 2;
                int col = n0 + wn * 64 + d0;
                int h = col >> 6;
                float bi00 = bias[col],      bi01 = bias[col + 1];
                float bi10 = bias[col + 32], bi11 = bias[col + 33];
                float if0 = powf(10000.0f, -(float)d0 * (1.0f / 32.0f));
                float if1 = powf(10000.0f, -(float)(d0 + 1) * (1.0f / 32.0f));
#pragma unroll
                for (int mf = 0; mf < 2; mf++) {
                    int rbase = m0 + wm * 32 + mf * 16 + (lane >> 2);
#pragma unroll
                    for (int half_ = 0; half_ < 2; half_++) {
                        int r = rbase + half_ * 8;
                        int b = r >> 11, s = r & (SS - 1);
                        size_t base = (((size_t)(b * HH + h)) << 17) + ((size_t)s << 6);
                        float x00 = acc[mf][nf][2 * half_]     + bi00;
                        float x01 = acc[mf][nf][2 * half_ + 1] + bi01;
                        float x10 = acc[mf][nf + 4][2 * half_]     + bi10;
                        float x11 = acc[mf][nf + 4][2 * half_ + 1] + bi11;
                        float sn0, cs0, sn1, cs1;
                        sincosf((float)s * if0, &sn0, &cs0);
                        sincosf((float)s * if1, &sn1, &cs1);
                        store2_h(OUT, base + d0,
                                 (x00 * cs0 - x10 * sn0) * osc,
                                 (x01 * cs1 - x11 * sn1) * osc);
                        store2_h(OUT, base + d0 + 32,
                                 (x10 * cs0 + x00 * sn0) * osc,
                                 (x11 * cs1 + x01 * sn1) * osc);
                    }
                }
            }
        } else {
#pragma unroll
            for (int nf = 0; nf < 8; nf++) {
                int col = n0 + wn * 64 + nf * 8 + (lane & 3) * 2;
                int h = col >> 6, d = col & 63;
                float b0 = bias[col], b1 = bias[col + 1];
#pragma unroll
                for (int mf = 0; mf < 2; mf++) {
                    int rbase = m0 + wm * 32 + mf * 16 + (lane >> 2);
#pragma unroll
                    for (int half_ = 0; half_ < 2; half_++) {
                        int r = rbase + half_ * 8;
                        int b = r >> 11, s = r & (SS - 1);
                        size_t base = (((size_t)(b * HH + h)) << 17) + ((size_t)s << 6);
                        store2_h(OUT, base + d,
                                 acc[mf][nf][2 * half_] + b0,
                                 acc[mf][nf][2 * half_ + 1] + b1);
                    }
                }
            }
        }
    }
#undef G_ISSUE
}

// ---------------------------------------------------------------------------
// Flash attention v3: 256 threads (8 warps), each warp owns 32 q-rows
// => q-block 256. One CTA/SM (launch_bounds(256,1)): SAME warp count as the
// best round-14 config, but each K/V fragment feeds 2 mf-groups, halving
// ldmatrix traffic per unit of tensor work, AND the K/V stage is shared by
// 256 q-rows, halving cp.async global traffic.
// Math identical to rounds 14/15: fp16-acc QK^T (log2 domain), ex2 in-place,
// fp32-acc PV + ones-mma L. 128-key blocks, 3-stage cp.async, one sync/iter.
// smem (128KB): Q 0..32K; stages at 32768 + st*32768 (K 16KB, V 16KB).
// ---------------------------------------------------------------------------
__global__ __launch_bounds__(256, 1) void mma_attn(
    const __half* __restrict__ Q, const __half* __restrict__ K,
    const __half* __restrict__ V, __half* __restrict__ Ctx)
{
    extern __shared__ __align__(1024) char sm[];
    const uint32_t smb = smem_u32(sm);
    const int tid = threadIdx.x;
    const int lane = tid & 31;
    const int warp = tid >> 5;          // 0..7, each owns 32 q-rows
    const int bh = blockIdx.y;
    const int q0 = blockIdx.x * 256;

    const size_t hb = ((size_t)bh << 17);
    const __half* Qp = Q + hb + (size_t)q0 * 64;
    const __half* tp[2] = { K + hb, V + hb };

    // ---- stage Q (256x64 fp16 = 2048 chunks): 8 chunks/thread
#pragma unroll
    for (int i = 0; i < 8; i++) {
        int unit = tid + i * 256;
        int row = unit >> 3, c = unit & 7;
        uint32_t dst = smb + row * 128 + (((c ^ (row & 7)) << 4));
        cpa16(dst, Qp + (size_t)row * 64 + c * 8);
    }
    CP_COMMIT();

    // K/V stage-load geometry: 8 chunks/thread (K 16KB + V 16KB per stage)
    int ktile[8], krow[8], kcol[8];
#pragma unroll
    for (int i = 0; i < 8; i++) {
        int unit = tid + i * 256;
        ktile[i] = unit >> 10;          // 0 = K, 1 = V
        int rem = unit & 1023;
        krow[i] = rem >> 3;
        kcol[i] = rem & 7;
    }

#define A_ISSUE(st, blk)                                                       \
    do {                                                                       \
        uint32_t stb_ = smb + 32768 + (st) * 32768;                            \
        _Pragma("unroll")                                                      \
        for (int i = 0; i < 8; i++) {                                          \
            uint32_t dst = stb_ + ktile[i] * 16384 + krow[i] * 128 +           \
                           (((kcol[i] ^ (krow[i] & 7)) << 4));                 \
            cpa16(dst, tp[ktile[i]] + ((size_t)((blk) * 128 + krow[i])) * 64 + kcol[i] * 8); \
        }                                                                      \
    } while (0)

    A_ISSUE(0, 0);
    CP_COMMIT();
    A_ISSUE(1, 1);
    CP_COMMIT();

    // ---- Q fragments persistent: 2 mf-groups x 4 kk
    CP_WAIT(2);
    __syncthreads();
    const int cQ = lane >> 4;
    uint32_t qf[2][4][4];
#pragma unroll
    for (int mf = 0; mf < 2; mf++) {
        int rowQ = warp * 32 + mf * 16 + (lane & 7) + ((lane >> 3) & 1) * 8;
#pragma unroll
        for (int kk = 0; kk < 4; kk++) {
            uint32_t off = smb + rowQ * 128 + (((2 * kk + cQ) ^ (rowQ & 7)) << 4);
            ldsm4(qf[mf][kk], off);
        }
    }

    float o[2][8][4];
#pragma unroll
    for (int mf = 0; mf < 2; mf++)
#pragma unroll
        for (int i = 0; i < 8; i++)
#pragma unroll
            for (int j = 0; j < 4; j++) o[mf][i][j] = 0.f;
    float accL[2][4];
#pragma unroll
    for (int mf = 0; mf < 2; mf++)
#pragma unroll
        for (int j = 0; j < 4; j++) accL[mf][j] = 0.f;
    const uint32_t ones2[2] = {0x3C003C00u, 0x3C003C00u};

    const int rK = (lane & 7) + (lane >> 4) * 8;
    const int cK = (lane >> 3) & 1;
    const int rV = (lane & 7) + ((lane >> 3) & 1) * 8;
    const int cV = lane >> 4;

    int stage = 0, stage2 = 2;
    for (int it = 0; it < 16; it++) {
        if (it < 15) { CP_WAIT(1); } else { CP_WAIT(0); }
        __syncthreads();
        if (it < 14) {
            A_ISSUE(stage2, it + 2);
            CP_COMMIT();
        }
        const uint32_t stb = smb + 32768 + stage * 32768;

#pragma unroll
        for (int h = 0; h < 2; h++) {       // two 64-key halves per block
            const uint32_t kb_ = stb + h * 8192;
            const uint32_t vb_ = stb + 16384 + h * 8192;

            // ---- S = Q K^T, fp16 accumulation; each K frag feeds BOTH mf
            uint32_t sh[2][8][2];
#pragma unroll
            for (int mf = 0; mf < 2; mf++)
#pragma unroll
                for (int i = 0; i < 8; i++) { sh[mf][i][0] = 0u; sh[mf][i][1] = 0u; }

#pragma unroll
            for (int kk = 0; kk < 4; kk++) {
#pragma unroll
                for (int nj = 0; nj < 4; nj++) {
                    int row = nj * 16 + rK;
                    uint32_t off = kb_ + row * 128 + (((2 * kk + cK) ^ (row & 7)) << 4);
                    uint32_t r4[4];
                    ldsm4(r4, off);
#pragma unroll
                    for (int mf = 0; mf < 2; mf++) {
                        mma16816hh(sh[mf][2 * nj],     qf[mf][kk], r4);
                        mma16816hh(sh[mf][2 * nj + 1], qf[mf][kk], r4 + 2);
                    }
                }
            }

            // ---- p = 2^s in-place on packed fp16x2 accumulators
            uint32_t ph[2][4][4];
#pragma unroll
            for (int mf = 0; mf < 2; mf++)
#pragma unroll
                for (int j = 0; j < 4; j++) {
                    ph[mf][j][0] = ex2r(sh[mf][2 * j][0]);
                    ph[mf][j][1] = ex2r(sh[mf][2 * j][1]);
                    ph[mf][j][2] = ex2r(sh[mf][2 * j + 1][0]);
                    ph[mf][j][3] = ex2r(sh[mf][2 * j + 1][1]);
                }

            // ---- O += P V; L += P·1; each V frag feeds BOTH mf
#pragma unroll
            for (int j = 0; j < 4; j++) {
                int row = j * 16 + rV;
#pragma unroll
                for (int u = 0; u < 4; u++) {
                    uint32_t off = vb_ + row * 128 + (((2 * u + cV) ^ (row & 7)) << 4);
                    uint32_t r4[4];
                    ldsm4t(r4, off);
#pragma unroll
                    for (int mf = 0; mf < 2; mf++) {
                        mma16816h(o[mf][2 * u],     ph[mf][j], r4);
                        mma16816h(o[mf][2 * u + 1], ph[mf][j], r4 + 2);
                    }
                }
#pragma unroll
                for (int mf = 0; mf < 2; mf++)
                    mma16816h(accL[mf], ph[mf][j], ones2);
            }
        }
        stage = (stage == 2) ? 0 : stage + 1;
        stage2 = (stage2 == 2) ? 0 : stage2 + 1;
    }

    // ---- writeout: Ctx fp16, [B*S, 1024]
    int b = bh >> 4, h = bh & 15;
#pragma unroll
    for (int mf = 0; mf < 2; mf++) {
        float inv0 = 1.f / accL[mf][0], inv1 = 1.f / accL[mf][2];
        int srow = q0 + warp * 32 + mf * 16 + (lane >> 2);
#pragma unroll
        for (int nf = 0; nf < 8; nf++) {
            int d = nf * 8 + (lane & 3) * 2;
            size_t off0 = ((size_t)(b * SS + srow)) * DD + h * 64 + d;
            store2_h(Ctx, off0, o[mf][nf][0] * inv0, o[mf][nf][1] * inv0);
            size_t off1 = ((size_t)(b * SS + srow + 8)) * DD + h * 64 + d;
            store2_h(Ctx, off1, o[mf][nf][2] * inv1, o[mf][nf][3] * inv1);
        }
    }
#undef A_ISSUE
}

// ---------------------------------------------------------------------------
extern "C" void kernel_launch(void* const* d_in, const int* in_sizes, int n_in,
                              void* d_out, int out_size)
{
    const float* query = (const float*)d_in[0];
    const float* key   = (const float*)d_in[1];
    const float* value = (const float*)d_in[2];
    const float* Wq    = (const float*)d_in[3];
    const float* bq    = (const float*)d_in[4];
    const float* Wk    = (const float*)d_in[5];
    const float* bk    = (const float*)d_in[6];
    const float* Wv    = (const float*)d_in[7];
    const float* bv    = (const float*)d_in[8];
    const float* Wo    = (const float*)d_in[9];
    const float* bo    = (const float*)d_in[10];

    __half *Ip, *Wp, *Qp, *Kp, *Vp;
    cudaGetSymbolAddress((void**)&Ip, g_I);
    cudaGetSymbolAddress((void**)&Wp, g_W);
    cudaGetSymbolAddress((void**)&Qp, g_Q);
    cudaGetSymbolAddress((void**)&Kp, g_K);
    cudaGetSymbolAddress((void**)&Vp, g_V);

    cudaFuncSetAttribute(mma_gemm<0>, cudaFuncAttributeMaxDynamicSharedMemorySize, 98304);
    cudaFuncSetAttribute(mma_gemm<1>, cudaFuncAttributeMaxDynamicSharedMemorySize, 98304);
    cudaFuncSetAttribute(mma_attn, cudaFuncAttributeMaxDynamicSharedMemorySize, 131072);

    // 1) convert inputs + weights to fp16 (one launch, MLP=4)
    const int total4 = (3 << 20) + (4 << 18);   // 4,194,304 float4s
    cvt_all_kernel<<<total4 / 1024, 256>>>(
        (const float4*)query, (const float4*)key, (const float4*)value,
        (const float4*)Wq, (const float4*)Wk, (const float4*)Wv, (const float4*)Wo,
        (ushort4*)Ip, (ushort4*)Wp);

    // 2) fused QKV projection + bias + RoPE (+QSCALE on Q) -> fp16 Q/K/V
    dim3 pg(DD / 128, MM / 128, 3);
    mma_gemm<1><<<pg, 256, 98304>>>(Ip, Wp, bq, bk, bv,
                                    nullptr, Qp, Kp, Vp);

    // 3) attention -> Ctx fp16 (reuse input buffer); q-block 256
    dim3 ag(SS / 256, BB * HH);     // (8, 32)
    mma_attn<<<ag, 256, 131072>>>(Qp, Kp, Vp, Ip);

    // 4) O projection -> d_out (fp32)
    dim3 og(DD / 128, MM / 128, 1);
    mma_gemm<0><<<og, 256, 98304>>>(Ip, Wp + (size_t)3 * DD * DD,
                                    bo, nullptr, nullptr,
                                    (float*)d_out, nullptr, nullptr, nullptr);
}